// round 3
// baseline (speedup 1.0000x reference)
#include <cuda_runtime.h>
#include <cuda_bf16.h>
#include <cstdint>

#define STATE_DIM 1024
#define NACT      256
#define MTILE     128
#define KC        64
#define NCHUNK    (STATE_DIM / KC)   // 16

// per-stage smem: Ahi 16K | Alo 16K | Bhi 32K | Blo 32K = 96KB
#define STAGE_BYTES 98304
#define A_LO_OFF    16384
#define B_HI_OFF    32768
#define B_LO_OFF    65536
#define SMEM_BYTES  (2 * STAGE_BYTES + 1024)

// Transformed weights, bf16 hi/lo split (256 x 1024 each)
__device__ __align__(16) __nv_bfloat16 g_Whi[NACT * STATE_DIM];
__device__ __align__(16) __nv_bfloat16 g_Wlo[NACT * STATE_DIM];

// ---------------- helpers ----------------
__device__ __forceinline__ uint32_t smem_u32(const void* p) {
    uint32_t a;
    asm("{ .reg .u64 t; cvta.to.shared.u64 t, %1; cvt.u32.u64 %0, t; }" : "=r"(a) : "l"(p));
    return a;
}

#define STS128(addr, v) asm volatile("st.shared.v4.b32 [%0], {%1,%2,%3,%4};" \
    :: "r"(addr), "r"((v).x), "r"((v).y), "r"((v).z), "r"((v).w) : "memory")

#define CP_ASYNC16(dst, src) asm volatile( \
    "cp.async.cg.shared.global [%0], [%1], 16;" :: "r"(dst), "l"(src) : "memory")
#define CP_COMMIT()  asm volatile("cp.async.commit_group;" ::: "memory")
#define CP_WAIT(n)   asm volatile("cp.async.wait_group %0;" :: "n"(n) : "memory")

__device__ __forceinline__ void ldm4(uint32_t* d, uint32_t addr) {
    asm volatile("ldmatrix.sync.aligned.m8n8.x4.shared.b16 {%0,%1,%2,%3}, [%4];"
        : "=r"(d[0]), "=r"(d[1]), "=r"(d[2]), "=r"(d[3]) : "r"(addr));
}

__device__ __forceinline__ void mma16816(float* c, const uint32_t* a, uint32_t b0, uint32_t b1) {
    asm volatile("mma.sync.aligned.m16n8k16.row.col.f32.bf16.bf16.f32 "
        "{%0,%1,%2,%3}, {%4,%5,%6,%7}, {%8,%9}, {%0,%1,%2,%3};"
        : "+f"(c[0]), "+f"(c[1]), "+f"(c[2]), "+f"(c[3])
        : "r"(a[0]), "r"(a[1]), "r"(a[2]), "r"(a[3]), "r"(b0), "r"(b1));
}

// split fp32 pair -> (bf16 hi pair, bf16 lo pair) packed into u32
__device__ __forceinline__ void split2(float a, float b, uint32_t& h, uint32_t& l) {
    __nv_bfloat162 hv = __floats2bfloat162_rn(a, b);
    float2 hf = __bfloat1622float2(hv);
    __nv_bfloat162 lv = __floats2bfloat162_rn(a - hf.x, b - hf.y);
    h = *reinterpret_cast<uint32_t*>(&hv);
    l = *reinterpret_cast<uint32_t*>(&lv);
}

// ---------------- prep: fold Hamilton transform into W, split bf16 hi/lo ----------------
__global__ void prep_kernel(const float* __restrict__ g, const float* __restrict__ W) {
    int a = blockIdx.x;    // action 0..255
    int n = threadIdx.x;   // quaternion group 0..255
    float4 gv = reinterpret_cast<const float4*>(g)[n];
    float qw = tanhf(gv.x), qi = tanhf(gv.y), qj = tanhf(gv.z), qk = tanhf(gv.w);
    float4 Wv = reinterpret_cast<const float4*>(W + (size_t)a * STATE_DIM)[n];
    float W0 = Wv.x, W1 = Wv.y, W2 = Wv.z, W3 = Wv.w;
    // logits = sum_i x_i * W'_i with W'_i = sum_j W_j * L[j][i]
    float o0 =  W0 * qw + W1 * qi + W2 * qj + W3 * qk;
    float o1 = -W0 * qi + W1 * qw + W2 * qk - W3 * qj;
    float o2 = -W0 * qj - W1 * qk + W2 * qw + W3 * qi;
    float o3 = -W0 * qk + W1 * qj - W2 * qi + W3 * qw;
    uint32_t h01, h23, l01, l23;
    split2(o0, o1, h01, l01);
    split2(o2, o3, h23, l23);
    reinterpret_cast<uint2*>(g_Whi)[a * 256 + n] = make_uint2(h01, h23);
    reinterpret_cast<uint2*>(g_Wlo)[a * 256 + n] = make_uint2(l01, l23);
}

// ---------------- main GEMM: out[B,256] = x[B,1024] @ W'^T + b ----------------
// 256 threads = 8 warps, warp grid 2(M) x 4(N), warp tile 64x64.
// 2-stage smem pipeline over 16 K-chunks of 64.
__global__ void __launch_bounds__(256, 1)
gemm_kernel(const float* __restrict__ x, const float* __restrict__ bias,
            float* __restrict__ out, int Btot) {
    extern __shared__ char smem[];
    const int tid  = threadIdx.x;
    const int wid  = tid >> 5;
    const int lane = tid & 31;
    const int wm   = wid >> 2;   // 0..1
    const int wn   = wid & 3;    // 0..3
    const int m0   = blockIdx.x * MTILE;

    const uint32_t sb    = smem_u32(smem);
    const uint32_t tiles = (sb + 1023u) & ~1023u;

    // ---- per-thread producer geometry ----
    const int prow = tid >> 3;            // 0..31 (row sub-index)
    const int pch  = tid & 7;             // 16B chunk within 128B row
    const uint32_t pswz = (uint32_t)((pch ^ (prow & 7)) << 4);
    const float4* xf4 = reinterpret_cast<const float4*>(x);
    const uint4*  bhf = reinterpret_cast<const uint4*>(g_Whi);
    const uint4*  blf = reinterpret_cast<const uint4*>(g_Wlo);

    // ---- ldmatrix lane geometry ----
    const int rA = (lane & 7) | (((lane >> 3) & 1) << 3);  // 0..15
    const int kA = lane >> 4;                              // 0..1
    const int rB = (lane & 7) | (((lane >> 4) & 1) << 3);
    const int kB = (lane >> 3) & 1;
    const uint32_t aRowOff = (uint32_t)((wm * 64 + rA) * 128);
    const uint32_t bRowOff = (uint32_t)((wn * 64 + rB) * 128);
    uint32_t aSwz[4], bSwz[4];
    #pragma unroll
    for (int ks = 0; ks < 4; ks++) {
        aSwz[ks] = (uint32_t)((((2 * ks + kA) ^ (rA & 7)) << 4));
        bSwz[ks] = (uint32_t)((((2 * ks + kB) ^ (rB & 7)) << 4));
    }

    float acc[4][8][4];
    #pragma unroll
    for (int m = 0; m < 4; m++)
        #pragma unroll
        for (int n = 0; n < 8; n++)
            #pragma unroll
            for (int q = 0; q < 4; q++) acc[m][n][q] = 0.0f;

    // ---- prologue: LDG A chunk0, cp.async B chunk0 ----
    float4 af[4][2];
    #pragma unroll
    for (int i = 0; i < 4; i++) {
        int row = 32 * i + prow;
        bool v = (m0 + row) < Btot;
        size_t base = (size_t)(m0 + row) * 256 + 2 * pch;   // float4 units
        af[i][0] = v ? xf4[base + 0] : make_float4(0.f, 0.f, 0.f, 0.f);
        af[i][1] = v ? xf4[base + 1] : make_float4(0.f, 0.f, 0.f, 0.f);
    }
    {
        const uint32_t st = tiles;
        #pragma unroll
        for (int i = 0; i < 8; i++) {
            int row = 32 * i + prow;
            uint32_t dst = st + (uint32_t)(row * 128) + pswz;
            size_t src = (size_t)row * 128 + pch;            // uint4 units, chunk 0
            CP_ASYNC16(dst + B_HI_OFF, (const void*)(bhf + src));
            CP_ASYNC16(dst + B_LO_OFF, (const void*)(blf + src));
        }
        CP_COMMIT();
    }

    // ---- main loop ----
    #pragma unroll 1
    for (int c = 0; c < NCHUNK; c++) {
        const int s = c & 1;
        const uint32_t As = tiles + (uint32_t)s * STAGE_BYTES;
        const uint32_t Bs = As + B_HI_OFF;

        // convert + STS A(c) into stage s (last reader of stage s was compute(c-2),
        // retired before iteration c-1's barrier -> safe)
        #pragma unroll
        for (int i = 0; i < 4; i++) {
            uint4 vh, vl;
            split2(af[i][0].x, af[i][0].y, vh.x, vl.x);
            split2(af[i][0].z, af[i][0].w, vh.y, vl.y);
            split2(af[i][1].x, af[i][1].y, vh.z, vl.z);
            split2(af[i][1].z, af[i][1].w, vh.w, vl.w);
            uint32_t ad = As + (uint32_t)((32 * i + prow) * 128) + pswz;
            STS128(ad, vh);
            STS128(ad + A_LO_OFF, vl);
        }

        // prefetch A(c+1) into registers (no smem hazard)
        if (c < NCHUNK - 1) {
            #pragma unroll
            for (int i = 0; i < 4; i++) {
                int row = 32 * i + prow;
                bool v = (m0 + row) < Btot;
                size_t base = (size_t)(m0 + row) * 256 + (c + 1) * 16 + 2 * pch;
                af[i][0] = v ? xf4[base + 0] : make_float4(0.f, 0.f, 0.f, 0.f);
                af[i][1] = v ? xf4[base + 1] : make_float4(0.f, 0.f, 0.f, 0.f);
            }
        }

        // B(c) must have landed; then barrier publishes A(c) STS + B(c) cp.async
        CP_WAIT(0);
        __syncthreads();

        // NOW safe to overwrite stage s^1 (compute(c-1) retired before the barrier):
        // issue cp.async B(c+1); it overlaps with compute(c) below.
        if (c < NCHUNK - 1) {
            const uint32_t nst = tiles + (uint32_t)(s ^ 1) * STAGE_BYTES;
            #pragma unroll
            for (int i = 0; i < 8; i++) {
                int row = 32 * i + prow;
                uint32_t dst = nst + (uint32_t)(row * 128) + pswz;
                size_t src = (size_t)row * 128 + (c + 1) * 8 + pch;
                CP_ASYNC16(dst + B_HI_OFF, (const void*)(bhf + src));
                CP_ASYNC16(dst + B_LO_OFF, (const void*)(blf + src));
            }
            CP_COMMIT();
        }

        // ---- compute chunk c: 3-term split, 4 K16 slices ----
        #pragma unroll
        for (int ks = 0; ks < 4; ks++) {
            uint32_t ah[4][4], bh[4][4], tt[4][4];
            #pragma unroll
            for (int m = 0; m < 4; m++)
                ldm4(ah[m], As + aRowOff + (uint32_t)(m * 2048) + aSwz[ks]);
            #pragma unroll
            for (int p = 0; p < 4; p++)
                ldm4(bh[p], Bs + bRowOff + (uint32_t)(p * 2048) + bSwz[ks]);
            #pragma unroll
            for (int m = 0; m < 4; m++)
                #pragma unroll
                for (int p = 0; p < 4; p++) {
                    mma16816(acc[m][2 * p],     ah[m], bh[p][0], bh[p][1]);
                    mma16816(acc[m][2 * p + 1], ah[m], bh[p][2], bh[p][3]);
                }
            // hi(A) * lo(B)
            #pragma unroll
            for (int p = 0; p < 4; p++)
                ldm4(tt[p], As + B_LO_OFF + bRowOff + (uint32_t)(p * 2048) + bSwz[ks]);
            #pragma unroll
            for (int m = 0; m < 4; m++)
                #pragma unroll
                for (int p = 0; p < 4; p++) {
                    mma16816(acc[m][2 * p],     ah[m], tt[p][0], tt[p][1]);
                    mma16816(acc[m][2 * p + 1], ah[m], tt[p][2], tt[p][3]);
                }
            // lo(A) * hi(B)
            #pragma unroll
            for (int m = 0; m < 4; m++)
                ldm4(tt[m], As + A_LO_OFF + aRowOff + (uint32_t)(m * 2048) + aSwz[ks]);
            #pragma unroll
            for (int m = 0; m < 4; m++)
                #pragma unroll
                for (int p = 0; p < 4; p++) {
                    mma16816(acc[m][2 * p],     tt[m], bh[p][0], bh[p][1]);
                    mma16816(acc[m][2 * p + 1], tt[m], bh[p][2], bh[p][3]);
                }
        }
    }

    // ---- epilogue: direct STG.64 with bias ----
    const int rrow = m0 + wm * 64 + (lane >> 2);
    const int cb   = wn * 64 + (lane & 3) * 2;
    float2 bv[8];
    #pragma unroll
    for (int n = 0; n < 8; n++)
        bv[n] = *reinterpret_cast<const float2*>(bias + cb + n * 8);
    #pragma unroll
    for (int m = 0; m < 4; m++) {
        int r1 = rrow + m * 16;
        int r2 = r1 + 8;
        #pragma unroll
        for (int n = 0; n < 8; n++) {
            int col = cb + n * 8;
            if (r1 < Btot) {
                float2 v = make_float2(acc[m][n][0] + bv[n].x, acc[m][n][1] + bv[n].y);
                *reinterpret_cast<float2*>(out + (size_t)r1 * NACT + col) = v;
            }
            if (r2 < Btot) {
                float2 v = make_float2(acc[m][n][2] + bv[n].x, acc[m][n][3] + bv[n].y);
                *reinterpret_cast<float2*>(out + (size_t)r2 * NACT + col) = v;
            }
        }
    }
}

// ---------------- launch ----------------
extern "C" void kernel_launch(void* const* d_in, const int* in_sizes, int n_in,
                              void* d_out, int out_size) {
    const float* x = (const float*)d_in[0];
    const float* g = (const float*)d_in[1];
    const float* W = (const float*)d_in[2];
    const float* b = (const float*)d_in[3];
    float* out = (float*)d_out;
    int Btot = in_sizes[0] / STATE_DIM;

    prep_kernel<<<NACT, 256>>>(g, W);

    cudaFuncSetAttribute(gemm_kernel, cudaFuncAttributeMaxDynamicSharedMemorySize, SMEM_BYTES);
    int grid = (Btot + MTILE - 1) / MTILE;
    gemm_kernel<<<grid, 256, SMEM_BYTES>>>(x, b, out, Btot);
}

// round 6
// speedup vs baseline: 1.0808x; 1.0808x over previous
#include <cuda_runtime.h>
#include <cuda_fp16.h>
#include <cstdint>

#define STATE_DIM 1024
#define NACT      256
#define MTILE     128
#define KC        64
#define NCHUNK    (STATE_DIM / KC)   // 16

// per-stage smem: A 16K | Bhi 32K | Blo 32K = 80KB
#define B_HI_OFF    16384
#define B_LO_OFF    49152
#define STAGE_BYTES 81920
#define SMEM_BYTES  (2 * STAGE_BYTES + 1024)

// Transformed weights, fp16 hi/lo split (256 x 1024 each)
__device__ __align__(16) __half g_Whi[NACT * STATE_DIM];
__device__ __align__(16) __half g_Wlo[NACT * STATE_DIM];

// ---------------- helpers ----------------
__device__ __forceinline__ uint32_t smem_u32(const void* p) {
    uint32_t a;
    asm("{ .reg .u64 t; cvta.to.shared.u64 t, %1; cvt.u32.u64 %0, t; }" : "=r"(a) : "l"(p));
    return a;
}

#define STS128(addr, v) asm volatile("st.shared.v4.b32 [%0], {%1,%2,%3,%4};" \
    :: "r"(addr), "r"((v).x), "r"((v).y), "r"((v).z), "r"((v).w) : "memory")

#define CP_ASYNC16(dst, src) asm volatile( \
    "cp.async.cg.shared.global [%0], [%1], 16;" :: "r"(dst), "l"(src) : "memory")
#define CP_COMMIT()  asm volatile("cp.async.commit_group;" ::: "memory")
#define CP_WAIT(n)   asm volatile("cp.async.wait_group %0;" :: "n"(n) : "memory")

__device__ __forceinline__ void ldm4(uint32_t* d, uint32_t addr) {
    asm volatile("ldmatrix.sync.aligned.m8n8.x4.shared.b16 {%0,%1,%2,%3}, [%4];"
        : "=r"(d[0]), "=r"(d[1]), "=r"(d[2]), "=r"(d[3]) : "r"(addr));
}

__device__ __forceinline__ void mma16816(float* c, const uint32_t* a, uint32_t b0, uint32_t b1) {
    asm volatile("mma.sync.aligned.m16n8k16.row.col.f32.f16.f16.f32 "
        "{%0,%1,%2,%3}, {%4,%5,%6,%7}, {%8,%9}, {%0,%1,%2,%3};"
        : "+f"(c[0]), "+f"(c[1]), "+f"(c[2]), "+f"(c[3])
        : "r"(a[0]), "r"(a[1]), "r"(a[2]), "r"(a[3]), "r"(b0), "r"(b1));
}

// fp32 pair -> packed fp16 pair
__device__ __forceinline__ uint32_t pack_h2(float a, float b) {
    __half2 h = __floats2half2_rn(a, b);
    return *reinterpret_cast<uint32_t*>(&h);
}
// fp32 pair -> (hi fp16 pair, lo fp16 pair)
__device__ __forceinline__ void split2h(float a, float b, uint32_t& h, uint32_t& l) {
    __half2 hv = __floats2half2_rn(a, b);
    float2 hf = __half22float2(hv);
    __half2 lv = __floats2half2_rn(a - hf.x, b - hf.y);
    h = *reinterpret_cast<uint32_t*>(&hv);
    l = *reinterpret_cast<uint32_t*>(&lv);
}

// ---------------- prep: fold Hamilton transform into W, split fp16 hi/lo ----------------
__global__ void prep_kernel(const float* __restrict__ g, const float* __restrict__ W) {
    int a = blockIdx.x;    // action 0..255
    int n = threadIdx.x;   // quaternion group 0..255
    float4 gv = reinterpret_cast<const float4*>(g)[n];
    float qw = tanhf(gv.x), qi = tanhf(gv.y), qj = tanhf(gv.z), qk = tanhf(gv.w);
    float4 Wv = reinterpret_cast<const float4*>(W + (size_t)a * STATE_DIM)[n];
    float W0 = Wv.x, W1 = Wv.y, W2 = Wv.z, W3 = Wv.w;
    // logits = sum_i x_i * W'_i with W'_i = sum_j W_j * L[j][i]
    float o0 =  W0 * qw + W1 * qi + W2 * qj + W3 * qk;
    float o1 = -W0 * qi + W1 * qw + W2 * qk - W3 * qj;
    float o2 = -W0 * qj - W1 * qk + W2 * qw + W3 * qi;
    float o3 = -W0 * qk + W1 * qj - W2 * qi + W3 * qw;
    uint32_t h01, h23, l01, l23;
    split2h(o0, o1, h01, l01);
    split2h(o2, o3, h23, l23);
    reinterpret_cast<uint2*>(g_Whi)[a * 256 + n] = make_uint2(h01, h23);
    reinterpret_cast<uint2*>(g_Wlo)[a * 256 + n] = make_uint2(l01, l23);
}

// ---------------- main GEMM: out[B,256] = x[B,1024] @ W'^T + b ----------------
// 512 threads = 16 warps, warp grid 2(M) x 8(N), warp tile 64x32.
// 2-stage smem pipeline over 16 K-chunks of 64. 2-term fp16 split (A fp16, B hi+lo).
__global__ void __launch_bounds__(512, 1)
gemm_kernel(const float* __restrict__ x, const float* __restrict__ bias,
            float* __restrict__ out, int Btot) {
    extern __shared__ char smem[];
    const int tid  = threadIdx.x;
    const int wid  = tid >> 5;
    const int lane = tid & 31;
    const int wm   = wid >> 3;   // 0..1
    const int wn   = wid & 7;    // 0..7
    const int m0   = blockIdx.x * MTILE;

    const uint32_t sb    = smem_u32(smem);
    const uint32_t tiles = (sb + 1023u) & ~1023u;

    // ---- producer geometry ----
    // A: 128 rows x 8 chunks(16B fp16). thread -> row tid>>2, chunks (tid&3), (tid&3)+4
    const int  apr = tid >> 2;
    const int  apq = tid & 3;
    // B: 256 rows x 8 chunks x {hi,lo}. thread -> row tid>>1, 4 chunks at (tid&1)*4+q
    const int  bpr = tid >> 1;
    const int  bpq = (tid & 1) * 4;
    const float4* xf4 = reinterpret_cast<const float4*>(x);
    const uint4*  bhf = reinterpret_cast<const uint4*>(g_Whi);
    const uint4*  blf = reinterpret_cast<const uint4*>(g_Wlo);

    const long aRowG = (long)m0 + apr;
    const bool aval  = aRowG < (long)Btot;

    // ---- ldmatrix lane geometry ----
    const int rA = (lane & 7) | (((lane >> 3) & 1) << 3);  // 0..15
    const int kA = lane >> 4;                              // 0..1
    const int rB = (lane & 7) | (((lane >> 4) & 1) << 3);
    const int kB = (lane >> 3) & 1;
    const uint32_t aRowOff = (uint32_t)((wm * 64 + rA) * 128);
    const uint32_t bRowOff = (uint32_t)((wn * 32 + rB) * 128);
    uint32_t aSwz[4], bSwz[4];
    #pragma unroll
    for (int ks = 0; ks < 4; ks++) {
        aSwz[ks] = (uint32_t)((((2 * ks + kA) ^ (rA & 7)) << 4));
        bSwz[ks] = (uint32_t)((((2 * ks + kB) ^ (rB & 7)) << 4));
    }

    float acc[4][4][4];
    #pragma unroll
    for (int m = 0; m < 4; m++)
        #pragma unroll
        for (int n = 0; n < 4; n++)
            #pragma unroll
            for (int q = 0; q < 4; q++) acc[m][n][q] = 0.0f;

    // ---- prologue: LDG A chunk0 into regs, cp.async B chunk0 ----
    float4 af[4];   // 2 chunks x 2 float4
    {
        size_t base = (size_t)aRowG * 256;   // float4 units per row of 1024 floats
        #pragma unroll
        for (int h = 0; h < 2; h++) {
            int ch = apq + 4 * h;
            af[2*h+0] = aval ? xf4[base + ch * 2 + 0] : make_float4(0.f,0.f,0.f,0.f);
            af[2*h+1] = aval ? xf4[base + ch * 2 + 1] : make_float4(0.f,0.f,0.f,0.f);
        }
    }
    {
        #pragma unroll
        for (int q = 0; q < 4; q++) {
            int ch = bpq + q;
            uint32_t dst = tiles + (uint32_t)(bpr * 128) + (uint32_t)(((ch ^ (bpr & 7)) << 4));
            size_t src = (size_t)bpr * 128 + ch;   // uint4 units, chunk 0
            CP_ASYNC16(dst + B_HI_OFF, (const void*)(bhf + src));
            CP_ASYNC16(dst + B_LO_OFF, (const void*)(blf + src));
        }
        CP_COMMIT();
    }

    // ---- main loop ----
    #pragma unroll 1
    for (int c = 0; c < NCHUNK; c++) {
        const int s = c & 1;
        const uint32_t As = tiles + (uint32_t)s * STAGE_BYTES;
        const uint32_t Bs = As + B_HI_OFF;

        // convert + STS A(c) into stage s (stage's last reader retired at prev barrier)
        #pragma unroll
        for (int h = 0; h < 2; h++) {
            int ch = apq + 4 * h;
            uint4 v;
            v.x = pack_h2(af[2*h+0].x, af[2*h+0].y);
            v.y = pack_h2(af[2*h+0].z, af[2*h+0].w);
            v.z = pack_h2(af[2*h+1].x, af[2*h+1].y);
            v.w = pack_h2(af[2*h+1].z, af[2*h+1].w);
            uint32_t ad = As + (uint32_t)(apr * 128) + (uint32_t)(((ch ^ (apr & 7)) << 4));
            STS128(ad, v);
        }

        // prefetch A(c+1) into registers
        if (c < NCHUNK - 1) {
            size_t base = (size_t)aRowG * 256 + (size_t)(c + 1) * 16;
            #pragma unroll
            for (int h = 0; h < 2; h++) {
                int ch = apq + 4 * h;
                af[2*h+0] = aval ? xf4[base + ch * 2 + 0] : make_float4(0.f,0.f,0.f,0.f);
                af[2*h+1] = aval ? xf4[base + ch * 2 + 1] : make_float4(0.f,0.f,0.f,0.f);
            }
        }

        // B(c) landed; publish A(c) STS + B(c)
        CP_WAIT(0);
        __syncthreads();

        // stage s^1 free now: issue cp.async B(c+1), overlaps compute(c)
        if (c < NCHUNK - 1) {
            const uint32_t nst = tiles + (uint32_t)(s ^ 1) * STAGE_BYTES;
            #pragma unroll
            for (int q = 0; q < 4; q++) {
                int ch = bpq + q;
                uint32_t dst = nst + (uint32_t)(bpr * 128) + (uint32_t)(((ch ^ (bpr & 7)) << 4));
                size_t src = (size_t)bpr * 128 + (size_t)(c + 1) * 8 + ch;
                CP_ASYNC16(dst + B_HI_OFF, (const void*)(bhf + src));
                CP_ASYNC16(dst + B_LO_OFF, (const void*)(blf + src));
            }
            CP_COMMIT();
        }

        // ---- compute chunk c: 2-term fp16 split, 4 K16 slices ----
        #pragma unroll
        for (int ks = 0; ks < 4; ks++) {
            uint32_t ah[4][4], bh[2][4], bl[2][4];
            #pragma unroll
            for (int m = 0; m < 4; m++)
                ldm4(ah[m], As + aRowOff + (uint32_t)(m * 2048) + aSwz[ks]);
            #pragma unroll
            for (int p = 0; p < 2; p++) {
                ldm4(bh[p], Bs + bRowOff + (uint32_t)(p * 2048) + bSwz[ks]);
                ldm4(bl[p], Bs + (B_LO_OFF - B_HI_OFF) + bRowOff + (uint32_t)(p * 2048) + bSwz[ks]);
            }
            #pragma unroll
            for (int m = 0; m < 4; m++)
                #pragma unroll
                for (int p = 0; p < 2; p++) {
                    mma16816(acc[m][2 * p],     ah[m], bh[p][0], bh[p][1]);
                    mma16816(acc[m][2 * p + 1], ah[m], bh[p][2], bh[p][3]);
                    mma16816(acc[m][2 * p],     ah[m], bl[p][0], bl[p][1]);
                    mma16816(acc[m][2 * p + 1], ah[m], bl[p][2], bl[p][3]);
                }
        }
    }

    // ---- epilogue: direct STG.64 with bias ----
    const int rrow = m0 + wm * 64 + (lane >> 2);
    const int cb   = wn * 32 + (lane & 3) * 2;
    float2 bv[4];
    #pragma unroll
    for (int n = 0; n < 4; n++)
        bv[n] = *reinterpret_cast<const float2*>(bias + cb + n * 8);
    #pragma unroll
    for (int m = 0; m < 4; m++) {
        int r1 = rrow + m * 16;
        int r2 = r1 + 8;
        #pragma unroll
        for (int n = 0; n < 4; n++) {
            int col = cb + n * 8;
            if (r1 < Btot) {
                float2 v = make_float2(acc[m][n][0] + bv[n].x, acc[m][n][1] + bv[n].y);
                *reinterpret_cast<float2*>(out + (size_t)r1 * NACT + col) = v;
            }
            if (r2 < Btot) {
                float2 v = make_float2(acc[m][n][2] + bv[n].x, acc[m][n][3] + bv[n].y);
                *reinterpret_cast<float2*>(out + (size_t)r2 * NACT + col) = v;
            }
        }
    }
}

// ---------------- launch ----------------
extern "C" void kernel_launch(void* const* d_in, const int* in_sizes, int n_in,
                              void* d_out, int out_size) {
    const float* x = (const float*)d_in[0];
    const float* g = (const float*)d_in[1];
    const float* W = (const float*)d_in[2];
    const float* b = (const float*)d_in[3];
    float* out = (float*)d_out;
    int Btot = in_sizes[0] / STATE_DIM;

    prep_kernel<<<NACT, 256>>>(g, W);

    cudaFuncSetAttribute(gemm_kernel, cudaFuncAttributeMaxDynamicSharedMemorySize, SMEM_BYTES);
    int grid = (Btot + MTILE - 1) / MTILE;
    gemm_kernel<<<grid, 512, SMEM_BYTES>>>(x, b, out, Btot);
}

// round 7
// speedup vs baseline: 1.8509x; 1.7125x over previous
#include <cuda_runtime.h>
#include <cuda_fp16.h>
#include <cstdint>

#define STATE_DIM 1024
#define NACT      256
#define MTILE     128
#define KC        64
#define NCHUNK    (STATE_DIM / KC)   // 16
#define NSTAGE    3

// per-stage smem: A 16K | B 32K = 48KB
#define B_OFF       16384
#define STAGE_BYTES 49152
#define SMEM_BYTES  (NSTAGE * STAGE_BYTES + 1024)

// Transformed weights, fp16 (256 x 1024)
__device__ __align__(16) __half g_Wh[NACT * STATE_DIM];

// ---------------- helpers ----------------
__device__ __forceinline__ uint32_t smem_u32(const void* p) {
    uint32_t a;
    asm("{ .reg .u64 t; cvta.to.shared.u64 t, %1; cvt.u32.u64 %0, t; }" : "=r"(a) : "l"(p));
    return a;
}

#define STS128(addr, v) asm volatile("st.shared.v4.b32 [%0], {%1,%2,%3,%4};" \
    :: "r"(addr), "r"((v).x), "r"((v).y), "r"((v).z), "r"((v).w) : "memory")

#define CP_ASYNC16(dst, src) asm volatile( \
    "cp.async.cg.shared.global [%0], [%1], 16;" :: "r"(dst), "l"(src) : "memory")
#define CP_COMMIT()  asm volatile("cp.async.commit_group;" ::: "memory")
#define CP_WAIT(n)   asm volatile("cp.async.wait_group %0;" :: "n"(n) : "memory")

__device__ __forceinline__ void ldm4(uint32_t* d, uint32_t addr) {
    asm volatile("ldmatrix.sync.aligned.m8n8.x4.shared.b16 {%0,%1,%2,%3}, [%4];"
        : "=r"(d[0]), "=r"(d[1]), "=r"(d[2]), "=r"(d[3]) : "r"(addr));
}

__device__ __forceinline__ void mma16816(float* c, const uint32_t* a, uint32_t b0, uint32_t b1) {
    asm volatile("mma.sync.aligned.m16n8k16.row.col.f32.f16.f16.f32 "
        "{%0,%1,%2,%3}, {%4,%5,%6,%7}, {%8,%9}, {%0,%1,%2,%3};"
        : "+f"(c[0]), "+f"(c[1]), "+f"(c[2]), "+f"(c[3])
        : "r"(a[0]), "r"(a[1]), "r"(a[2]), "r"(a[3]), "r"(b0), "r"(b1));
}

// fp32 pair -> packed fp16 pair
__device__ __forceinline__ uint32_t pack_h2(float a, float b) {
    __half2 h = __floats2half2_rn(a, b);
    return *reinterpret_cast<uint32_t*>(&h);
}

// ---------------- prep: fold Hamilton transform into W, convert fp16 ----------------
__global__ void prep_kernel(const float* __restrict__ g, const float* __restrict__ W) {
    int a = blockIdx.x;    // action 0..255
    int n = threadIdx.x;   // quaternion group 0..255
    float4 gv = reinterpret_cast<const float4*>(g)[n];
    float qw = tanhf(gv.x), qi = tanhf(gv.y), qj = tanhf(gv.z), qk = tanhf(gv.w);
    float4 Wv = reinterpret_cast<const float4*>(W + (size_t)a * STATE_DIM)[n];
    float W0 = Wv.x, W1 = Wv.y, W2 = Wv.z, W3 = Wv.w;
    // logits = sum_i x_i * W'_i with W'_i = sum_j W_j * L[j][i]
    float o0 =  W0 * qw + W1 * qi + W2 * qj + W3 * qk;
    float o1 = -W0 * qi + W1 * qw + W2 * qk - W3 * qj;
    float o2 = -W0 * qj - W1 * qk + W2 * qw + W3 * qi;
    float o3 = -W0 * qk + W1 * qj - W2 * qi + W3 * qw;
    reinterpret_cast<uint2*>(g_Wh)[a * 256 + n] =
        make_uint2(pack_h2(o0, o1), pack_h2(o2, o3));
}

// ---------------- main GEMM: out[B,256] = x[B,1024] @ W'^T + b ----------------
// 512 threads = 16 warps, warp grid 2(M) x 8(N), warp tile 64x32.
// 3-stage cp.async pipeline, distance-2 B prefetch, single-term fp16.
__global__ void __launch_bounds__(512, 1)
gemm_kernel(const float* __restrict__ x, const float* __restrict__ bias,
            float* __restrict__ out, int Btot) {
    extern __shared__ char smem[];
    const int tid  = threadIdx.x;
    const int wid  = tid >> 5;
    const int lane = tid & 31;
    const int wm   = wid >> 3;   // 0..1
    const int wn   = wid & 7;    // 0..7
    const int m0   = blockIdx.x * MTILE;

    const uint32_t sb    = smem_u32(smem);
    const uint32_t tiles = (sb + 1023u) & ~1023u;

    // ---- producer geometry ----
    // A: 128 rows x 8 chunks(16B). thread -> row tid>>2, chunks (tid&3), (tid&3)+4
    const int  apr = tid >> 2;
    const int  apq = tid & 3;
    // B: 256 rows x 8 chunks. thread -> row tid>>1, 4 chunks at (tid&1)*4+q
    const int  bpr = tid >> 1;
    const int  bpq = (tid & 1) * 4;
    const float4* xf4 = reinterpret_cast<const float4*>(x);
    const uint4*  bwf = reinterpret_cast<const uint4*>(g_Wh);

    const long aRowG = (long)m0 + apr;
    const bool aval  = aRowG < (long)Btot;

    // ---- ldmatrix lane geometry ----
    const int rA = (lane & 7) | (((lane >> 3) & 1) << 3);  // 0..15
    const int kA = lane >> 4;                              // 0..1
    const int rB = (lane & 7) | (((lane >> 4) & 1) << 3);
    const int kB = (lane >> 3) & 1;
    const uint32_t aRowOff = (uint32_t)((wm * 64 + rA) * 128);
    const uint32_t bRowOff = (uint32_t)((wn * 32 + rB) * 128);
    uint32_t aSwz[4], bSwz[4];
    #pragma unroll
    for (int ks = 0; ks < 4; ks++) {
        aSwz[ks] = (uint32_t)((((2 * ks + kA) ^ (rA & 7)) << 4));
        bSwz[ks] = (uint32_t)((((2 * ks + kB) ^ (rB & 7)) << 4));
    }

    float acc[4][4][4];
    #pragma unroll
    for (int m = 0; m < 4; m++)
        #pragma unroll
        for (int n = 0; n < 4; n++)
            #pragma unroll
            for (int q = 0; q < 4; q++) acc[m][n][q] = 0.0f;

    // B cp.async issue for chunk c into stage st
    auto issueB = [&](int c, uint32_t st) {
        #pragma unroll
        for (int q = 0; q < 4; q++) {
            int ch = bpq + q;
            uint32_t dst = st + B_OFF + (uint32_t)(bpr * 128)
                         + (uint32_t)(((ch ^ (bpr & 7)) << 4));
            size_t src = (size_t)bpr * 128 + (size_t)c * 8 + ch;   // uint4 units
            CP_ASYNC16(dst, (const void*)(bwf + src));
        }
        CP_COMMIT();
    };

    // ---- prologue: LDG A(0) into regs; B(0), B(1) in flight ----
    float4 af[4];
    {
        size_t base = (size_t)aRowG * 256;
        #pragma unroll
        for (int h = 0; h < 2; h++) {
            int ch = apq + 4 * h;
            af[2*h+0] = aval ? xf4[base + ch * 2 + 0] : make_float4(0.f,0.f,0.f,0.f);
            af[2*h+1] = aval ? xf4[base + ch * 2 + 1] : make_float4(0.f,0.f,0.f,0.f);
        }
    }
    issueB(0, tiles);
    issueB(1, tiles + STAGE_BYTES);

    // ---- main loop ----
    #pragma unroll 1
    for (int c = 0; c < NCHUNK; c++) {
        const int s = c % NSTAGE;
        const uint32_t As = tiles + (uint32_t)s * STAGE_BYTES;
        const uint32_t Bs = As + B_OFF;

        // convert + STS A(c) into stage s (A(c-3) readers retired 2 barriers ago)
        #pragma unroll
        for (int h = 0; h < 2; h++) {
            int ch = apq + 4 * h;
            uint4 v;
            v.x = pack_h2(af[2*h+0].x, af[2*h+0].y);
            v.y = pack_h2(af[2*h+0].z, af[2*h+0].w);
            v.z = pack_h2(af[2*h+1].x, af[2*h+1].y);
            v.w = pack_h2(af[2*h+1].z, af[2*h+1].w);
            uint32_t ad = As + (uint32_t)(apr * 128) + (uint32_t)(((ch ^ (apr & 7)) << 4));
            STS128(ad, v);
        }

        // prefetch A(c+1) into registers
        if (c < NCHUNK - 1) {
            size_t base = (size_t)aRowG * 256 + (size_t)(c + 1) * 16;
            #pragma unroll
            for (int h = 0; h < 2; h++) {
                int ch = apq + 4 * h;
                af[2*h+0] = aval ? xf4[base + ch * 2 + 0] : make_float4(0.f,0.f,0.f,0.f);
                af[2*h+1] = aval ? xf4[base + ch * 2 + 1] : make_float4(0.f,0.f,0.f,0.f);
            }
        }

        // B(c) landed (B(c+1) may still be in flight); publish A(c) STS
        if (c < NCHUNK - 1) { CP_WAIT(1); } else { CP_WAIT(0); }
        __syncthreads();

        // stage (c+2)%3 = (c-1)%3 is free (compute(c-1) retired before this barrier)
        if (c + 2 < NCHUNK)
            issueB(c + 2, tiles + (uint32_t)((c + 2) % NSTAGE) * STAGE_BYTES);

        // ---- compute chunk c: single-term fp16, 4 K16 slices ----
        #pragma unroll
        for (int ks = 0; ks < 4; ks++) {
            uint32_t ah[4][4], bh[2][4];
            #pragma unroll
            for (int m = 0; m < 4; m++)
                ldm4(ah[m], As + aRowOff + (uint32_t)(m * 2048) + aSwz[ks]);
            #pragma unroll
            for (int p = 0; p < 2; p++)
                ldm4(bh[p], Bs + bRowOff + (uint32_t)(p * 2048) + bSwz[ks]);
            #pragma unroll
            for (int m = 0; m < 4; m++)
                #pragma unroll
                for (int p = 0; p < 2; p++) {
                    mma16816(acc[m][2 * p],     ah[m], bh[p][0], bh[p][1]);
                    mma16816(acc[m][2 * p + 1], ah[m], bh[p][2], bh[p][3]);
                }
        }
    }

    // ---- epilogue: direct STG.64 with bias ----
    const int rrow = m0 + wm * 64 + (lane >> 2);
    const int cb   = wn * 32 + (lane & 3) * 2;
    float2 bv[4];
    #pragma unroll
    for (int n = 0; n < 4; n++)
        bv[n] = *reinterpret_cast<const float2*>(bias + cb + n * 8);
    #pragma unroll
    for (int m = 0; m < 4; m++) {
        int r1 = rrow + m * 16;
        int r2 = r1 + 8;
        #pragma unroll
        for (int n = 0; n < 4; n++) {
            int col = cb + n * 8;
            if (r1 < Btot) {
                float2 v = make_float2(acc[m][n][0] + bv[n].x, acc[m][n][1] + bv[n].y);
                *reinterpret_cast<float2*>(out + (size_t)r1 * NACT + col) = v;
            }
            if (r2 < Btot) {
                float2 v = make_float2(acc[m][n][2] + bv[n].x, acc[m][n][3] + bv[n].y);
                *reinterpret_cast<float2*>(out + (size_t)r2 * NACT + col) = v;
            }
        }
    }
}

// ---------------- launch ----------------
extern "C" void kernel_launch(void* const* d_in, const int* in_sizes, int n_in,
                              void* d_out, int out_size) {
    const float* x = (const float*)d_in[0];
    const float* g = (const float*)d_in[1];
    const float* W = (const float*)d_in[2];
    const float* b = (const float*)d_in[3];
    float* out = (float*)d_out;
    int Btot = in_sizes[0] / STATE_DIM;

    prep_kernel<<<NACT, 256>>>(g, W);

    cudaFuncSetAttribute(gemm_kernel, cudaFuncAttributeMaxDynamicSharedMemorySize, SMEM_BYTES);
    int grid = (Btot + MTILE - 1) / MTILE;
    gemm_kernel<<<grid, 512, SMEM_BYTES>>>(x, b, out, Btot);
}